// round 14
// baseline (speedup 1.0000x reference)
#include <cuda_runtime.h>
#include <cuda_bf16.h>
#include <math.h>

// ---------------- static problem sizes ----------------
#define N_TREES 128
#define DEPTH   10
#define NODES_PER_TREE 1023      // 2^10 - 1
#define NC 16                    // C states
#define NM 256                   // M symbols
#define NL 2                     // child positions
#define NG 8                     // generators

typedef unsigned long long ull;
union U2 { ull u; float2 f; };
union F4 { float4 f; ull u[2]; };

// ---------------- normalized parameters (device globals, no alloc) ----------
__device__ float g_An [NG][NL][NC][NC];   // softmax_a(lambda_A)*SP (SP folded)
__device__ float g_Bn [NG][NM][NC];       // softmax_m(lambda_B), [g][m][c]
__device__ float g_Pin[NG][NL][NC];       // softmax_c(lambda_Pi)

// ---------------- packed f32x2 helpers (sm_103a FFMA2) ----------------
__device__ __forceinline__ ull ffma2(ull a, ull b, ull c) {
    ull d;
    asm("fma.rn.f32x2 %0, %1, %2, %3;" : "=l"(d) : "l"(a), "l"(b), "l"(c));
    return d;
}
__device__ __forceinline__ ull fadd2(ull a, ull b) {
    ull d;
    asm("add.rn.f32x2 %0, %1, %2;" : "=l"(d) : "l"(a), "l"(b));
    return d;
}

// ---------------- prep1: parallelized softmaxes ----------------
// grid (NG, 17), 256 threads. y<16: B softmax row c=y. y==16: A + Pi.
__global__ void htmm_prep1(const float* __restrict__ lA,
                           const float* __restrict__ lB,
                           const float* __restrict__ lPi,
                           const float* __restrict__ lSP) {
    const int g   = blockIdx.x;
    const int y   = blockIdx.y;
    const int tid = threadIdx.x;

    if (y < NC) {
        __shared__ float red[16];
        const int wid  = tid >> 5;
        const int lane = tid & 31;
        float v = lB[(((y << 8) + tid) << 3) + g];

        float m = v;
        #pragma unroll
        for (int o = 16; o; o >>= 1)
            m = fmaxf(m, __shfl_xor_sync(0xffffffffu, m, o));
        if (lane == 0) red[wid] = m;
        __syncthreads();
        float mx = red[0];
        #pragma unroll
        for (int i = 1; i < 8; i++) mx = fmaxf(mx, red[i]);

        float e = expf(v - mx);
        float s = e;
        #pragma unroll
        for (int o = 16; o; o >>= 1)
            s += __shfl_xor_sync(0xffffffffu, s, o);
        if (lane == 0) red[8 + wid] = s;
        __syncthreads();
        float sum = red[8];
        #pragma unroll
        for (int i = 1; i < 8; i++) sum += red[8 + i];

        g_Bn[g][tid][y] = e / sum;
        return;
    }

    float a0 = lSP[g], a1 = lSP[8 + g];
    float mxs = fmaxf(a0, a1);
    float e0 = expf(a0 - mxs), e1 = expf(a1 - mxs);
    float inv = 1.0f / (e0 + e1);
    float sp0 = e0 * inv, sp1 = e1 * inv;

    if (tid < 32) {
        int b = tid >> 1, l = tid & 1;
        float v[NC];
        float m = -3.0e38f;
        #pragma unroll
        for (int a = 0; a < NC; a++) {
            v[a] = lA[((a * 16 + b) * 2 + l) * 8 + g];
            m = fmaxf(m, v[a]);
        }
        float s = 0.0f;
        #pragma unroll
        for (int a = 0; a < NC; a++) { v[a] = expf(v[a] - m); s += v[a]; }
        float scale = (l ? sp1 : sp0) / s;
        #pragma unroll
        for (int a = 0; a < NC; a++) g_An[g][l][b][a] = v[a] * scale;
    } else if (tid < 34) {
        int l = tid - 32;
        float v[NC];
        float m = -3.0e38f;
        #pragma unroll
        for (int c = 0; c < NC; c++) {
            v[c] = lPi[(c * 2 + l) * 8 + g];
            m = fmaxf(m, v[c]);
        }
        float s = 0.0f;
        #pragma unroll
        for (int c = 0; c < NC; c++) { v[c] = expf(v[c] - m); s += v[c]; }
        float isum = 1.0f / s;
        #pragma unroll
        for (int c = 0; c < NC; c++) g_Pin[g][l][c] = v[c] * isum;
    }
}

// ---------------- half-warp (width-16) sum ----------------
__device__ __forceinline__ float hsum16(float v) {
    #pragma unroll
    for (int o = 8; o; o >>= 1) v += __shfl_xor_sync(0xffffffffu, v, o, 16);
    return v;
}

// pair contraction returning per-child partials:
// r.x = sum_b A0[lane,b]*bufL[b], r.y = sum_b A1[lane,b]*bufR[b]
__device__ __forceinline__ float2 contract2p(const float4* __restrict__ cv,
                                             const ull* __restrict__ rA2) {
    ull a0 = 0ull, a1 = 0ull;
    #pragma unroll
    for (int k = 0; k < 8; k++) {
        F4 q; q.f = cv[k];                    // b = 2k and 2k+1
        a0 = ffma2(rA2[2 * k],     q.u[0], a0);
        a1 = ffma2(rA2[2 * k + 1], q.u[1], a1);
    }
    U2 r; r.u = fadd2(a0, a1);
    return r.f;
}

// LAZY level step: children stored UNNORMALIZED with per-node 1/nu scalars.
// t = rx*invL + ry*invR reproduces the reference normalized contraction
// exactly; this node stores v unnormalized + its own 1/nu. The hsum sits
// OFF the level-to-level critical path. Returns nu (1.0 when inactive).
__device__ __forceinline__ float level_node(const float* __restrict__ child,
                                            const float2* __restrict__ cInv,
                                            float* __restrict__ parent,
                                            float* __restrict__ pInv,
                                            int P, int firstn, int i, bool act,
                                            const int* __restrict__ xs,
                                            const float* __restrict__ Bg,
                                            const ull* __restrict__ rA2,
                                            int lane) {
    int ic = act ? i : (P - 1);               // clamp: lanes stay convergent
    float2 r  = contract2p((const float4*)(child + (ic << 5)), rA2);
    float2 ci = cInv[ic];                     // (1/nu_L, 1/nu_R) broadcast
    float t   = fmaf(r.x, ci.x, r.y * ci.y);
    int   xv  = xs[firstn + ic];
    float v   = t * Bg[(xv << 4) + lane];
    float nu  = hsum16(v);
    if (act && P > 1) {
        parent[((i >> 1) << 5) + 2 * lane + (i & 1)] = v;   // unnormalized
        float inv = __fdividef(1.0f, nu);
        if (lane == 0) pInv[i] = inv;         // flat view of float2 array
    }
    return act ? nu : 1.0f;
}

// group-local level: CNT consecutive nodes from base_i; chunks of <=4 give
// MLP~4 and batch the log (nus are reference-magnitude, prod4 safe in fp32).
template <int CNT>
__device__ __forceinline__ void group_level(const float* __restrict__ child,
                                            const float2* __restrict__ cInv,
                                            float* __restrict__ parent,
                                            float* __restrict__ pInv,
                                            int P, int firstn, int base_i,
                                            const int* __restrict__ xs,
                                            const float* __restrict__ Bg,
                                            const ull* __restrict__ rA2,
                                            int lane, float& ll) {
    constexpr int CH = (CNT >= 4) ? 4 : CNT;
    for (int c = 0; c < CNT; c += CH) {
        float prod = 1.0f;
        #pragma unroll
        for (int k = 0; k < CH; k++)
            prod *= level_node(child, cInv, parent, pInv, P, firstn,
                               base_i + c + k, true, xs, Bg, rA2, lane);
        float lg = __logf(prod);
        if (lane == 0) ll += lg;
    }
}

// ---------------- main kernel: one block per (tree, gen) ----------------
// 128 threads = 8 groups of 16 lanes; half-warp owns one node; lane = state.
// Blocked subtree ownership for locality; __syncthreads at every buffer-reuse
// boundary (P=64..P=8) — writes there reuse regions other warps may still be
// reading at the previous level (WAR hazard __syncwarp does NOT cover).
__global__ __launch_bounds__(128, 7)
void htmm_main(const int* __restrict__ x, float* __restrict__ out) {
    __shared__ float  bufA[256 * NC];         // 16 KB
    __shared__ float  bufB[128 * NC];         // 8 KB
    __shared__ float2 nuA[128];               // 1 KB  (1/nu per node, paired)
    __shared__ float2 nuB[64];                // 0.5 KB
    __shared__ float  stg[8 * 2 * 32];        // 2 KB leaf staging
    __shared__ int    xs[NODES_PER_TREE];     // 4 KB
    __shared__ float  wsum[4];

    const int tid  = threadIdx.x;
    const int lane = tid & 15;                // state a
    const int grp  = tid >> 4;                // 0..7
    const int g    = blockIdx.x & 7;
    const int tree = blockIdx.x >> 3;
    const int base = tree * NODES_PER_TREE;
    const unsigned hmask = 0xFFFFu << (tid & 16);
    const float* __restrict__ Bg = &g_Bn[g][0][0];

    #pragma unroll
    for (int j = tid; j < NODES_PER_TREE; j += 128) xs[j] = x[base + j];

    ull rA2[NC];
    #pragma unroll
    for (int b = 0; b < NC; b++) {
        U2 t; t.f = make_float2(g_An[g][0][b][lane], g_An[g][1][b][lane]);
        rA2[b] = t.u;
    }
    const float piL = g_Pin[g][0][lane];
    const float piR = g_Pin[g][1][lane];
    __syncthreads();                          // xs ready

    float ll = 0.0f;

    // -------- fused stage: leaves + level-8 parents [32g, 32g+32) --------
    // Leaf normalizers computed INLINE via hsum16 (== old S-table exactly):
    // nuL = sum_c Pi[c,0]*B[c,xL] = hsum16(vL). Shfl chain (MIO pipe)
    // overlaps the FFMA2 contraction; no S table, no prep2 launch.
    {
        int it = 0;
        #pragma unroll 2
        for (int k = 0; k < 32; k++, it ^= 1) {
            int i  = (grp << 5) + k;
            int xL = xs[511 + 2 * i], xR = xs[512 + 2 * i];
            int xp = xs[255 + i];
            float vL = piL * Bg[(xL << 4) + lane];   // RAW leaf values
            float vR = piR * Bg[(xR << 4) + lane];
            float* sb = stg + ((grp << 1) + it) * 32;
            *(float2*)(sb + 2 * lane) = make_float2(vL, vR);
            float nuL = hsum16(vL);           // off critical path (MIO)
            float nuR = hsum16(vR);
            float invL = __fdividef(1.0f, nuL);
            float invR = __fdividef(1.0f, nuR);
            __syncwarp(hmask);
            float2 r = contract2p((const float4*)sb, rA2);
            float t  = fmaf(r.x, invL, r.y * invR);  // normalized combine
            float v  = t * Bg[(xp << 4) + lane];
            float nu = hsum16(v);
            bufA[((i >> 1) << 5) + 2 * lane + (i & 1)] = v;  // unnormalized
            float inv = __fdividef(1.0f, nu);
            float lg  = __logf(nuL * nuR * nu);
            if (lane == 0) {
                ((float*)nuA)[i] = inv;
                ll += lg;
            }
        }
    }
    __syncwarp();   // P=128 reads only this group's own bufA/nuA pairs

    // -------- descent: P = 128, 64, 32, 16, 8 --------
    group_level<16>(bufA, nuA, bufB, (float*)nuB, 128, 127, grp << 4,
                    xs, Bg, rA2, lane, ll);
    __syncthreads();   // P=64 writes bufA regions other warps read at P=128
    group_level< 8>(bufB, nuB, bufA, (float*)nuA,  64,  63, grp << 3,
                    xs, Bg, rA2, lane, ll);
    __syncthreads();
    group_level< 4>(bufA, nuA, bufB, (float*)nuB,  32,  31, grp << 2,
                    xs, Bg, rA2, lane, ll);
    __syncthreads();
    group_level< 2>(bufB, nuB, bufA, (float*)nuA,  16,  15, grp << 1,
                    xs, Bg, rA2, lane, ll);
    __syncthreads();
    group_level< 1>(bufA, nuA, bufB, (float*)nuB,   8,   7, grp,
                    xs, Bg, rA2, lane, ll);
    __syncthreads();   // warp 0 consumes pairs written by warps 0..3

    // -------- warp-collapsed top levels: P = 4, 2, 1 on warp 0 only --------
    if (tid < 32) {                           // groups 0,1
        float n0 = level_node(bufB, nuB, bufA, (float*)nuA, 4, 3, grp,
                              true, xs, Bg, rA2, lane);
        float n1 = level_node(bufB, nuB, bufA, (float*)nuA, 4, 3, grp + 2,
                              true, xs, Bg, rA2, lane);
        __syncwarp();
        float n2 = level_node(bufA, nuA, bufB, (float*)nuB, 2, 1, grp,
                              true, xs, Bg, rA2, lane);
        __syncwarp();
        float n3 = level_node(bufB, nuB, bufA, (float*)nuA, 1, 0, grp,
                              grp == 0, xs, Bg, rA2, lane);
        float lg = __logf(n0 * n1 * n2 * n3);
        if (lane == 0) ll += lg;
    }

    // -------- block reduction of ll --------
    #pragma unroll
    for (int o = 16; o; o >>= 1) ll += __shfl_xor_sync(0xffffffffu, ll, o);
    if ((tid & 31) == 0) wsum[tid >> 5] = ll;
    __syncthreads();
    if (tid == 0)
        out[blockIdx.x] = wsum[0] + wsum[1] + wsum[2] + wsum[3];
}

// ---------------- launch ----------------
extern "C" void kernel_launch(void* const* d_in, const int* in_sizes, int n_in,
                              void* d_out, int out_size) {
    const float* lA  = (const float*)d_in[0];   // lambda_A  (C,C,L,G)
    const float* lB  = (const float*)d_in[1];   // lambda_B  (C,M,G)
    const float* lPi = (const float*)d_in[2];   // lambda_Pi (C,L,G)
    const float* lSP = (const float*)d_in[3];   // lambda_SP (L,G)
    const int*   x   = (const int*)  d_in[4];   // x (N,)
    float* out = (float*)d_out;                 // (N_TREES, N_GEN)

    cudaFuncSetAttribute(htmm_main,
                         cudaFuncAttributePreferredSharedMemoryCarveout, 100);

    dim3 grid1(NG, NC + 1);
    htmm_prep1<<<grid1, 256>>>(lA, lB, lPi, lSP);
    htmm_main<<<N_TREES * NG, 128>>>(x, out);
}

// round 16
// speedup vs baseline: 1.3508x; 1.3508x over previous
#include <cuda_runtime.h>
#include <cuda_bf16.h>
#include <math.h>

// ---------------- static problem sizes ----------------
#define N_TREES 128
#define NODES_PER_TREE 1023
#define NC 16
#define NM 256
#define NL 2
#define NG 8

typedef unsigned long long ull;
typedef unsigned char uchar;
union U2 { ull u; float2 f; };
union F4 { float4 f; ull u[2]; };

// ---------------- normalized parameters ----------------
__device__ float g_An [NG][NL][NC][NC];   // softmax_a(lambda_A)*SP folded
__device__ float g_Bn [NG][NM][NC];       // softmax_m(lambda_B), [g][m][c]
__device__ float g_Pin[NG][NL][NC];
__device__ float g_S  [NG][NL][NM];       // leaf normalizer table

// ---------------- packed f32x2 helpers ----------------
__device__ __forceinline__ ull ffma2(ull a, ull b, ull c) {
    ull d;
    asm("fma.rn.f32x2 %0, %1, %2, %3;" : "=l"(d) : "l"(a), "l"(b), "l"(c));
    return d;
}
__device__ __forceinline__ ull fadd2(ull a, ull b) {
    ull d;
    asm("add.rn.f32x2 %0, %1, %2;" : "=l"(d) : "l"(a), "l"(b));
    return d;
}

// ---------------- prep1: parallel softmaxes ----------------
__global__ void htmm_prep1(const float* __restrict__ lA,
                           const float* __restrict__ lB,
                           const float* __restrict__ lPi,
                           const float* __restrict__ lSP) {
    const int g   = blockIdx.x;
    const int y   = blockIdx.y;
    const int tid = threadIdx.x;

    if (y < NC) {
        __shared__ float red[16];
        const int wid  = tid >> 5;
        const int lane = tid & 31;
        float v = lB[(((y << 8) + tid) << 3) + g];
        float m = v;
        #pragma unroll
        for (int o = 16; o; o >>= 1)
            m = fmaxf(m, __shfl_xor_sync(0xffffffffu, m, o));
        if (lane == 0) red[wid] = m;
        __syncthreads();
        float mx = red[0];
        #pragma unroll
        for (int i = 1; i < 8; i++) mx = fmaxf(mx, red[i]);
        float e = expf(v - mx);
        float s = e;
        #pragma unroll
        for (int o = 16; o; o >>= 1)
            s += __shfl_xor_sync(0xffffffffu, s, o);
        if (lane == 0) red[8 + wid] = s;
        __syncthreads();
        float sum = red[8];
        #pragma unroll
        for (int i = 1; i < 8; i++) sum += red[8 + i];
        g_Bn[g][tid][y] = e / sum;
        return;
    }

    float a0 = lSP[g], a1 = lSP[8 + g];
    float mxs = fmaxf(a0, a1);
    float e0 = expf(a0 - mxs), e1 = expf(a1 - mxs);
    float inv = 1.0f / (e0 + e1);
    float sp0 = e0 * inv, sp1 = e1 * inv;

    if (tid < 32) {
        int b = tid >> 1, l = tid & 1;
        float v[NC];
        float m = -3.0e38f;
        #pragma unroll
        for (int a = 0; a < NC; a++) {
            v[a] = lA[((a * 16 + b) * 2 + l) * 8 + g];
            m = fmaxf(m, v[a]);
        }
        float s = 0.0f;
        #pragma unroll
        for (int a = 0; a < NC; a++) { v[a] = expf(v[a] - m); s += v[a]; }
        float scale = (l ? sp1 : sp0) / s;
        #pragma unroll
        for (int a = 0; a < NC; a++) g_An[g][l][b][a] = v[a] * scale;
    } else if (tid < 34) {
        int l = tid - 32;
        float v[NC];
        float m = -3.0e38f;
        #pragma unroll
        for (int c = 0; c < NC; c++) {
            v[c] = lPi[(c * 2 + l) * 8 + g];
            m = fmaxf(m, v[c]);
        }
        float s = 0.0f;
        #pragma unroll
        for (int c = 0; c < NC; c++) { v[c] = expf(v[c] - m); s += v[c]; }
        float isum = 1.0f / s;
        #pragma unroll
        for (int c = 0; c < NC; c++) g_Pin[g][l][c] = v[c] * isum;
    }
}

// ---------------- prep2: leaf-normalizer table ----------------
__global__ void htmm_prep2() {
    const int g = blockIdx.x;
    const int m = threadIdx.x;
    float s0 = 0.0f, s1 = 0.0f;
    #pragma unroll
    for (int c = 0; c < NC; c++) {
        float b = g_Bn[g][m][c];
        s0 = fmaf(g_Pin[g][0][c], b, s0);
        s1 = fmaf(g_Pin[g][1][c], b, s1);
    }
    g_S[g][0][m] = s0;
    g_S[g][1][m] = s1;
}

// ---------------- half-warp sum ----------------
__device__ __forceinline__ float hsum16(float v) {
    #pragma unroll
    for (int o = 8; o; o >>= 1) v += __shfl_xor_sync(0xffffffffu, v, o, 16);
    return v;
}

// pair contraction: sum over both pair lanes (children stored NORMALIZED)
__device__ __forceinline__ float contract2(const float4* __restrict__ cv,
                                           const ull* __restrict__ rA2) {
    ull a0 = 0ull, a1 = 0ull;
    #pragma unroll
    for (int k = 0; k < 8; k++) {
        F4 q; q.f = cv[k];
        a0 = ffma2(rA2[2 * k],     q.u[0], a0);
        a1 = ffma2(rA2[2 * k + 1], q.u[1], a1);
    }
    U2 r; r.u = fadd2(a0, a1);
    return r.f.x + r.f.y;
}

// one node: child pair cpair (in `child`), writes parent pair ppair slot
// (ppair<0 -> no store, root). Returns nu (1.0 inactive).
__device__ __forceinline__ float level_node(const float* __restrict__ child,
                                            float* __restrict__ parent,
                                            int cpair, int ppair, int slot,
                                            int nodeidx, bool act,
                                            const uchar* __restrict__ xs,
                                            const float* __restrict__ Bg,
                                            const ull* __restrict__ rA2,
                                            int lane) {
    float t  = contract2((const float4*)(child + (cpair << 5)), rA2);
    int   xv = xs[nodeidx];
    float v  = t * Bg[(xv << 4) + lane];
    float nu = hsum16(v);
    if (act && ppair >= 0)
        parent[(ppair << 5) + 2 * lane + slot] = __fdividef(v, nu);
    return act ? nu : 1.0f;
}

// ---------------- main: one block per (tree, gen) ----------------
// 128 threads = 8 half-warp groups; lane = state. SLAB-REMAPPED descent:
// every level's writes stay inside the group's own slab (bufA pairs
// [16g,16g+16), bufB pairs [8g,8g+8)), so P=128..16 are race-free under
// __syncwarp. Only P=8 merges across sibling groups into bufB pairs 0..3
// -> __syncthreads before and after it.
__global__ __launch_bounds__(128, 8)
void htmm_main(const int* __restrict__ x, float* __restrict__ out) {
    __shared__ __align__(16) float bufA[128 * 32];   // 16 KB (128 pairs)
    __shared__ __align__(16) float bufB[64 * 32];    // 8 KB  (64 pairs)
    __shared__ __align__(16) float stg[8 * 2 * 32];  // 2 KB leaf staging
    __shared__ uchar xs[1024];                       // 1 KB symbols (M<=256)
    __shared__ float wsum[4];

    const int tid  = threadIdx.x;
    const int lane = tid & 15;
    const int grp  = tid >> 4;
    const int g    = blockIdx.x & 7;
    const int tree = blockIdx.x >> 3;
    const int base = tree * NODES_PER_TREE;
    const unsigned hmask = 0xFFFFu << (tid & 16);
    const float* __restrict__ Bg = &g_Bn[g][0][0];
    const float* __restrict__ S0 = &g_S[g][0][0];
    const float* __restrict__ S1 = &g_S[g][1][0];

    #pragma unroll
    for (int j = tid; j < NODES_PER_TREE; j += 128)
        xs[j] = (uchar)x[base + j];

    ull rA2[NC];
    #pragma unroll
    for (int b = 0; b < NC; b++) {
        U2 t; t.f = make_float2(g_An[g][0][b][lane], g_An[g][1][b][lane]);
        rA2[b] = t.u;
    }
    const float piL = g_Pin[g][0][lane];
    const float piR = g_Pin[g][1][lane];
    __syncthreads();                          // xs ready

    float ll = 0.0f;

    // -------- leaves + level-8 parents i in [32g,32g+32) --------
    // writes bufA pair i>>1 in [16g,16g+16): own slab
    {
        int it = 0;
        #pragma unroll 2
        for (int k = 0; k < 32; k++, it ^= 1) {
            int i  = (grp << 5) + k;
            int xL = xs[511 + 2 * i], xR = xs[512 + 2 * i];
            int xp = xs[255 + i];
            float sL = S0[xL], sR = S1[xR];   // table normalizers
            float vL = __fdividef(piL * Bg[(xL << 4) + lane], sL);
            float vR = __fdividef(piR * Bg[(xR << 4) + lane], sR);
            float* sb = stg + ((grp << 1) + it) * 32;
            *(float2*)(sb + 2 * lane) = make_float2(vL, vR);
            __syncwarp(hmask);
            float t  = contract2((const float4*)sb, rA2);
            float v  = t * Bg[(xp << 4) + lane];
            float nu = hsum16(v);
            bufA[((i >> 1) << 5) + 2 * lane + (i & 1)] = __fdividef(v, nu);
            float lg = __logf(sL * sR * nu);
            if (lane == 0) ll += lg;
        }
    }
    __syncwarp();

    // -------- P=128: i in [16g,16g+16); read bufA pair i, write bufB i>>1
    for (int c = 0; c < 16; c += 4) {
        float prod = 1.0f;
        #pragma unroll
        for (int k = 0; k < 4; k++) {
            int i = (grp << 4) + c + k;
            prod *= level_node(bufA, bufB, i, i >> 1, i & 1, 127 + i,
                               true, xs, Bg, rA2, lane);
        }
        float lg = __logf(prod);
        if (lane == 0) ll += lg;
    }
    __syncwarp();

    // -------- P=64: i in [8g,8g+8); read bufB pair i,
    //          write bufA pair 16g + ((i>>1)&3)  (own slab remap)
    for (int c = 0; c < 8; c += 4) {
        float prod = 1.0f;
        #pragma unroll
        for (int k = 0; k < 4; k++) {
            int i = (grp << 3) + c + k;
            int pp = (grp << 4) + ((i >> 1) & 3);
            prod *= level_node(bufB, bufA, i, pp, i & 1, 63 + i,
                               true, xs, Bg, rA2, lane);
        }
        float lg = __logf(prod);
        if (lane == 0) ll += lg;
    }
    __syncwarp();

    // -------- P=32: i in [4g,4g+4); read bufA pair 16g+(i&3),
    //          write bufB pair 8g + ((i>>1)&1)
    {
        float prod = 1.0f;
        #pragma unroll
        for (int k = 0; k < 4; k++) {
            int i  = (grp << 2) + k;
            int cp = (grp << 4) + (i & 3);
            int pp = (grp << 3) + ((i >> 1) & 1);
            prod *= level_node(bufA, bufB, cp, pp, i & 1, 31 + i,
                               true, xs, Bg, rA2, lane);
        }
        float lg = __logf(prod);
        if (lane == 0) ll += lg;
    }
    __syncwarp();

    // -------- P=16: i in [2g,2g+2); read bufB pair 8g+(i&1),
    //          write bufA pair 16g (both nodes, slots)
    {
        float prod = 1.0f;
        #pragma unroll
        for (int k = 0; k < 2; k++) {
            int i  = (grp << 1) + k;
            int cp = (grp << 3) + (i & 1);
            prod *= level_node(bufB, bufA, cp, grp << 4, i & 1, 15 + i,
                               true, xs, Bg, rA2, lane);
        }
        // -------- P=8: node 7+g; read bufA pair 16g; write bufB pair g>>1
        // (crosses slabs -> barriers around it)
        __syncthreads();
        float n8 = level_node(bufA, bufB, grp << 4, grp >> 1, grp & 1,
                              7 + grp, true, xs, Bg, rA2, lane);
        float lg = __logf(prod * n8);
        if (lane == 0) ll += lg;
    }
    __syncthreads();   // warp-0 phase consumes bufB pairs 0..3

    // -------- warp-collapsed top: P=4,2,1 on warp 0 --------
    if (tid < 32) {
        float n0 = level_node(bufB, bufA, grp,     grp >> 1,       grp & 1,
                              3 + grp,     true, xs, Bg, rA2, lane);
        float n1 = level_node(bufB, bufA, grp + 2, (grp + 2) >> 1, grp & 1,
                              5 + grp,     true, xs, Bg, rA2, lane);
        __syncwarp();
        float n2 = level_node(bufA, bufB, grp, 0, grp & 1,
                              1 + grp,     true, xs, Bg, rA2, lane);
        __syncwarp();
        float n3 = level_node(bufB, bufA, 0, -1, 0,
                              0, grp == 0, xs, Bg, rA2, lane);
        float lg = __logf(n0 * n1 * n2 * n3);
        if (lane == 0) ll += lg;
    }

    // -------- block reduction --------
    #pragma unroll
    for (int o = 16; o; o >>= 1) ll += __shfl_xor_sync(0xffffffffu, ll, o);
    if ((tid & 31) == 0) wsum[tid >> 5] = ll;
    __syncthreads();
    if (tid == 0)
        out[blockIdx.x] = wsum[0] + wsum[1] + wsum[2] + wsum[3];
}

// ---------------- launch ----------------
extern "C" void kernel_launch(void* const* d_in, const int* in_sizes, int n_in,
                              void* d_out, int out_size) {
    const float* lA  = (const float*)d_in[0];
    const float* lB  = (const float*)d_in[1];
    const float* lPi = (const float*)d_in[2];
    const float* lSP = (const float*)d_in[3];
    const int*   x   = (const int*)  d_in[4];
    float* out = (float*)d_out;

    cudaFuncSetAttribute(htmm_main,
                         cudaFuncAttributePreferredSharedMemoryCarveout, 100);

    dim3 grid1(NG, NC + 1);
    htmm_prep1<<<grid1, 256>>>(lA, lB, lPi, lSP);
    htmm_prep2<<<NG, 256>>>();
    htmm_main<<<N_TREES * NG, 128>>>(x, out);
}